// round 2
// baseline (speedup 1.0000x reference)
#include <cuda_runtime.h>

// VectorQuantizer on GB300 (sm_103a) — Round 2: FFMA2 (fma.rn.f32x2) inner loop
// inputs  : d_in[0] = X [16,1024,256] f32  (N=16384, D=256)
//           d_in[1] = E [8192,256]    f32  (K=8192)
// output  : d_out f32 = [ quantized_sg (N*D) | indices (N) | loss (1) | perplexity (1) ]

#define N_TOK  16384
#define D_DIM  256
#define K_CODE 8192

#define BM 64                   // rows per block
#define BN 128                  // codes per k-tile
#define BK 32                   // D chunk per stage
#define BK2 (BK / 2)            // f32x2 pairs per stage
#define XS_STRIDE (D_DIM + 4)   // 260 floats: float4-aligned rows, bank-spread
#define BS2S 130                // Bs2 row stride in float2 (1040B: 16B-aligned, spreads banks)

#define GATHER_BLOCKS (N_TOK / 8)

typedef unsigned long long u64;

__device__ float g_esq[K_CODE];
__device__ int   g_idx[N_TOK];
__device__ int   g_counts[K_CODE];
__device__ float g_blocksum[GATHER_BLOCKS];

// ---- f32x2 helpers (FFMA2 path; ptxas never auto-fuses) ----
__device__ __forceinline__ void ffma2(u64& d, u64 a, u64 b) {
    asm("fma.rn.f32x2 %0, %1, %2, %0;" : "+l"(d) : "l"(a), "l"(b));
}
__device__ __forceinline__ float2 u2f(u64 v) {
    float2 f;
    asm("mov.b64 {%0, %1}, %2;" : "=f"(f.x), "=f"(f.y) : "l"(v));
    return f;
}

// ---------------------------------------------------------------- zero
__global__ void vq_zero_kernel() {
    int t = blockIdx.x * blockDim.x + threadIdx.x;
    if (t < K_CODE) g_counts[t] = 0;
}

// ---------------------------------------------------------------- ||e||^2
__global__ void vq_esq_kernel(const float* __restrict__ E) {
    int gwarp = (blockIdx.x * blockDim.x + threadIdx.x) >> 5;
    int lane  = threadIdx.x & 31;
    if (gwarp >= K_CODE) return;
    const float* row = E + (size_t)gwarp * D_DIM;
    float s = 0.f;
#pragma unroll
    for (int q = 0; q < D_DIM / 32; ++q) {
        float v = row[lane + 32 * q];
        s = fmaf(v, v, s);
    }
#pragma unroll
    for (int o = 16; o; o >>= 1) s += __shfl_xor_sync(0xffffffffu, s, o);
    if (lane == 0) g_esq[gwarp] = s;
}

// ---------------------------------------------------------------- distances + argmin
// score(n,k) = ||e_k||^2 - 2 <x_n, e_k>  (same argmin ordering as reference)
__global__ __launch_bounds__(256, 2)
void vq_argmin_kernel(const float* __restrict__ X, const float* __restrict__ E) {
    extern __shared__ float smem[];
    float*  Xs   = smem;                                  // [BM][XS_STRIDE] floats
    float2* Bs2  = (float2*)(smem + BM * XS_STRIDE);      // [BK2][BS2S] float2 (d-pairs, code-major)
    float*  sEsq = (float*)(Bs2 + BK2 * BS2S);            // [BN]

    const int tid = threadIdx.x;
    const int tx  = tid & 15;     // 8 codes each
    const int ty  = tid >> 4;     // 4 rows each
    const int rowBase = blockIdx.x * BM;

    // Resident X tile [64][256], float4 loads, padded stores.
    {
        const float4* Xg = (const float4*)(X + (size_t)rowBase * D_DIM);
#pragma unroll
        for (int it = 0; it < 16; ++it) {
            int i4 = it * 256 + tid;
            int r  = i4 >> 6;
            int c4 = i4 & 63;
            float4 v = Xg[i4];
            *(float4*)(Xs + r * XS_STRIDE + c4 * 4) = v;
        }
    }

    float runMin[4];
    int   runIdx[4];
#pragma unroll
    for (int i = 0; i < 4; ++i) { runMin[i] = 3.4e38f; runIdx[i] = 0; }

    for (int kt = 0; kt < K_CODE / BN; ++kt) {
        if (tid < BN) sEsq[tid] = g_esq[kt * BN + tid];

        u64 acc[4][8];
#pragma unroll
        for (int i = 0; i < 4; ++i)
#pragma unroll
            for (int j = 0; j < 8; ++j) acc[i][j] = 0ULL;

        for (int dt = 0; dt < D_DIM / BK; ++dt) {       // 8 stages
            __syncthreads();   // Bs2 reuse safe (+ covers Xs/sEsq on first pass)
            // Load E chunk [BN codes][BK d] into Bs2 as d-pairs, code-major.
            {
                const float* Eg = E + (size_t)(kt * BN) * D_DIM + dt * BK;
#pragma unroll
                for (int q = 0; q < 4; ++q) {
                    int i4 = q * 256 + tid;       // 1024 float4s
                    int c  = i4 >> 3;             // code 0..127
                    int s4 = i4 & 7;              // float4 index within 32 d's
                    float4 v = *(const float4*)(Eg + (size_t)c * D_DIM + s4 * 4);
                    Bs2[(s4 * 2 + 0) * BS2S + c] = make_float2(v.x, v.y);
                    Bs2[(s4 * 2 + 1) * BS2S + c] = make_float2(v.z, v.w);
                }
            }
            __syncthreads();

#pragma unroll
            for (int kk2 = 0; kk2 < BK2; ++kk2) {
                u64 a2[4];
#pragma unroll
                for (int i = 0; i < 4; ++i)
                    a2[i] = *(const u64*)(Xs + (ty * 4 + i) * XS_STRIDE + dt * BK + 2 * kk2);
                const ulonglong2* bp = (const ulonglong2*)(Bs2 + kk2 * BS2S + tx * 8);
                ulonglong2 b01 = bp[0], b23 = bp[1], b45 = bp[2], b67 = bp[3];
                u64 b[8] = { b01.x, b01.y, b23.x, b23.y, b45.x, b45.y, b67.x, b67.y };
#pragma unroll
                for (int i = 0; i < 4; ++i)
#pragma unroll
                    for (int j = 0; j < 8; ++j)
                        ffma2(acc[i][j], a2[i], b[j]);
            }
        }

        // Epilogue: lane-combine + running argmin (strict < keeps earliest index)
#pragma unroll
        for (int j = 0; j < 8; ++j) {
            float eq  = sEsq[tx * 8 + j];
            int  code = kt * BN + tx * 8 + j;
#pragma unroll
            for (int i = 0; i < 4; ++i) {
                float2 d = u2f(acc[i][j]);
                float sc = fmaf(-2.f, d.x + d.y, eq);
                if (sc < runMin[i]) { runMin[i] = sc; runIdx[i] = code; }
            }
        }
        __syncthreads();   // before next kt overwrites sEsq/Bs2
    }

    // Cross-tx reduction per row; ties -> smaller index.
    float* sMin = (float*)Bs2;                 // 64*16 floats
    int*   sIdx = (int*)((float*)Bs2 + BM * 16);
#pragma unroll
    for (int i = 0; i < 4; ++i) {
        sMin[(ty * 4 + i) * 16 + tx] = runMin[i];
        sIdx[(ty * 4 + i) * 16 + tx] = runIdx[i];
    }
    __syncthreads();
    if (tid < BM) {
        float best = sMin[tid * 16];
        int   bi   = sIdx[tid * 16];
#pragma unroll
        for (int t = 1; t < 16; ++t) {
            float v  = sMin[tid * 16 + t];
            int   ix = sIdx[tid * 16 + t];
            if (v < best || (v == best && ix < bi)) { best = v; bi = ix; }
        }
        g_idx[rowBase + tid] = bi;
    }
}

// ---------------------------------------------------------------- gather + loss partials + counts
__global__ void vq_gather_kernel(const float* __restrict__ X, const float* __restrict__ E,
                                 float* __restrict__ outQ, float* __restrict__ outIdx,
                                 int writeExtras) {
    __shared__ float warpSums[8];
    int lwarp = threadIdx.x >> 5;
    int lane  = threadIdx.x & 31;
    int row   = blockIdx.x * 8 + lwarp;

    int idx = g_idx[row];
    const float4* e4 = (const float4*)(E + (size_t)idx * D_DIM);
    const float4* x4 = (const float4*)(X + (size_t)row * D_DIM);
    float4*       o4 = (float4*)(outQ + (size_t)row * D_DIM);

    float s = 0.f;
#pragma unroll
    for (int q = 0; q < 2; ++q) {
        float4 e = e4[lane + 32 * q];
        float4 x = x4[lane + 32 * q];
        float dx = e.x - x.x, dy = e.y - x.y, dz = e.z - x.z, dw = e.w - x.w;
        float4 o;
        o.x = x.x + dx; o.y = x.y + dy; o.z = x.z + dz; o.w = x.w + dw;
        o4[lane + 32 * q] = o;
        s += dx * dx + dy * dy + dz * dz + dw * dw;
    }
#pragma unroll
    for (int o = 16; o; o >>= 1) s += __shfl_xor_sync(0xffffffffu, s, o);
    if (lane == 0) {
        warpSums[lwarp] = s;
        atomicAdd(&g_counts[idx], 1);
        if (writeExtras) outIdx[row] = (float)idx;
    }
    __syncthreads();
    if (threadIdx.x == 0) {
        float bs = 0.f;
#pragma unroll
        for (int w = 0; w < 8; ++w) bs += warpSums[w];
        g_blocksum[blockIdx.x] = bs;
    }
}

// ---------------------------------------------------------------- finalize: loss + perplexity
__global__ void vq_finalize_kernel(float* __restrict__ outLoss, float* __restrict__ outPerp) {
    __shared__ float sh[256];
    int tid = threadIdx.x;

    float ss = 0.f;
    for (int b = tid; b < GATHER_BLOCKS; b += 256) ss += g_blocksum[b];
    sh[tid] = ss;
    __syncthreads();
    for (int o = 128; o; o >>= 1) {
        if (tid < o) sh[tid] += sh[tid + o];
        __syncthreads();
    }
    float sumsq = sh[0];
    __syncthreads();

    const float invN = 1.f / (float)N_TOK;
    float ent = 0.f;
    for (int k = tid; k < K_CODE; k += 256) {
        int c = g_counts[k];
        if (c > 0) {
            float p = (float)c * invN;
            ent += p * logf(p + 1e-10f);
        }
    }
    sh[tid] = ent;
    __syncthreads();
    for (int o = 128; o; o >>= 1) {
        if (tid < o) sh[tid] += sh[tid + o];
        __syncthreads();
    }
    if (tid == 0) {
        outLoss[0] = 0.25f * sumsq / (float)(N_TOK * D_DIM);
        outPerp[0] = expf(-sh[0]);
    }
}

// ---------------------------------------------------------------- launcher
extern "C" void kernel_launch(void* const* d_in, const int* in_sizes, int n_in,
                              void* d_out, int out_size) {
    const float* X = (const float*)d_in[0];
    const float* E = (const float*)d_in[1];
    float* out = (float*)d_out;

    float* outQ    = out;
    float* outIdx  = out + (size_t)N_TOK * D_DIM;
    float* outLoss = outIdx + N_TOK;
    float* outPerp = outLoss + 1;
    int writeExtras = (out_size >= N_TOK * D_DIM + N_TOK + 2) ? 1 : 0;

    const int smemBytes = (BM * XS_STRIDE) * (int)sizeof(float)
                        + (BK2 * BS2S) * (int)sizeof(float2)
                        + BN * (int)sizeof(float);
    cudaFuncSetAttribute(vq_argmin_kernel,
                         cudaFuncAttributeMaxDynamicSharedMemorySize, smemBytes);

    vq_zero_kernel<<<(K_CODE + 255) / 256, 256>>>();
    vq_esq_kernel<<<K_CODE / 8, 256>>>(E);
    vq_argmin_kernel<<<N_TOK / BM, 256, smemBytes>>>(X, E);
    vq_gather_kernel<<<GATHER_BLOCKS, 256>>>(X, E, outQ, outIdx, writeExtras);
    if (writeExtras) vq_finalize_kernel<<<1, 256>>>(outLoss, outPerp);
}

// round 4
// speedup vs baseline: 4.3621x; 4.3621x over previous
#include <cuda_runtime.h>
#include <cstdint>

// VectorQuantizer on GB300 (sm_103a) — Round 4: mma.sync tf32 (3x split) distance GEMM
// inputs  : d_in[0] = X [16,1024,256] f32  (N=16384, D=256)
//           d_in[1] = E [8192,256]    f32  (K=8192)
// output  : d_out f32 = [ quantized_sg (N*D) | indices (N) | loss (1) | perplexity (1) ]

#define N_TOK  16384
#define D_DIM  256
#define K_CODE 8192

#define BM 128                     // rows per CTA
#define BN 128                     // codes per CTA
#define KS 32                      // d per stage
#define N_STAGES (D_DIM / KS)      // 8
#define XS_ST 36                   // smem row stride (floats): conflict-free frags
#define TILE_FLOATS (128 * XS_ST)  // 4608 floats = 18432 B per tile
#define BUF_FLOATS (2 * TILE_FLOATS)  // X + E per buffer
#define SMEM_BYTES (2 * BUF_FLOATS * 4)  // 73728

#define N_CT (K_CODE / BN)         // 64 code tiles
#define GATHER_BLOCKS (N_TOK / 8)  // 2048

__device__ float g_esq[K_CODE];
__device__ float g_pmin[N_TOK * N_CT];
__device__ int   g_pidx[N_TOK * N_CT];
__device__ int   g_idx[N_TOK];
__device__ int   g_counts[K_CODE];
__device__ float g_blocksum[GATHER_BLOCKS];

// ============================ helpers ============================
__device__ __forceinline__ uint32_t smem_u32(const void* p) {
    uint32_t a;
    asm("{ .reg .u64 t; cvta.to.shared.u64 t, %1; cvt.u32.u64 %0, t; }" : "=r"(a) : "l"(p));
    return a;
}
__device__ __forceinline__ void cp16(uint32_t dst, const void* src) {
    asm volatile("cp.async.ca.shared.global [%0], [%1], 16;" :: "r"(dst), "l"(src));
}
__device__ __forceinline__ void tf32_split(float v, uint32_t& hi, uint32_t& lo) {
    asm("cvt.rna.tf32.f32 %0, %1;" : "=r"(hi) : "f"(v));
    float l = v - __uint_as_float(hi);
    asm("cvt.rna.tf32.f32 %0, %1;" : "=r"(lo) : "f"(l));
}
__device__ __forceinline__ void mma_tf32(float* d,
                                         uint32_t a0, uint32_t a1, uint32_t a2, uint32_t a3,
                                         uint32_t b0, uint32_t b1) {
    asm volatile(
        "mma.sync.aligned.m16n8k8.row.col.f32.tf32.tf32.f32 "
        "{%0,%1,%2,%3}, {%4,%5,%6,%7}, {%8,%9}, {%0,%1,%2,%3};"
        : "+f"(d[0]), "+f"(d[1]), "+f"(d[2]), "+f"(d[3])
        : "r"(a0), "r"(a1), "r"(a2), "r"(a3), "r"(b0), "r"(b1));
}

// ============================ prep kernels ============================
__global__ void vq_zero_kernel() {
    int t = blockIdx.x * blockDim.x + threadIdx.x;
    if (t < K_CODE) g_counts[t] = 0;
}

__global__ void vq_esq_kernel(const float* __restrict__ E) {
    int gwarp = (blockIdx.x * blockDim.x + threadIdx.x) >> 5;
    int lane  = threadIdx.x & 31;
    if (gwarp >= K_CODE) return;
    const float* row = E + (size_t)gwarp * D_DIM;
    float s = 0.f;
#pragma unroll
    for (int q = 0; q < D_DIM / 32; ++q) {
        float v = row[lane + 32 * q];
        s = fmaf(v, v, s);
    }
#pragma unroll
    for (int o = 16; o; o >>= 1) s += __shfl_xor_sync(0xffffffffu, s, o);
    if (lane == 0) g_esq[gwarp] = s;
}

// ============================ distance GEMM + partial argmin ============================
__global__ void __launch_bounds__(256, 2)
vq_mma_kernel(const float* __restrict__ X, const float* __restrict__ E) {
    extern __shared__ float smem[];
    const int tid  = threadIdx.x;
    const int wid  = tid >> 5;
    const int lane = tid & 31;
    const int quad = lane >> 2;     // 0..7
    const int qt   = lane & 3;      // 0..3
    const int warpRow = wid >> 2;   // 0..1  (64 rows each)
    const int warpCol = wid & 3;    // 0..3  (32 cols each)
    const int rowBase  = blockIdx.y * BM;
    const int codeBase = blockIdx.x * BN;
    const uint32_t sb = smem_u32(smem);

    float d[4][4][4];
#pragma unroll
    for (int mt = 0; mt < 4; ++mt)
#pragma unroll
        for (int nt = 0; nt < 4; ++nt)
#pragma unroll
            for (int r = 0; r < 4; ++r) d[mt][nt][r] = 0.f;

    // ---- async stage loader: X tile [128][KS] + E tile [128][KS], stride-36 rows ----
    auto issue = [&](int ks, int buf) {
        const float* xsrc = X + (size_t)rowBase * D_DIM + ks * KS;
        const float* esrc = E + (size_t)codeBase * D_DIM + ks * KS;
        uint32_t xdst = sb + (uint32_t)buf * (BUF_FLOATS * 4);
        uint32_t edst = xdst + TILE_FLOATS * 4;
#pragma unroll
        for (int q = 0; q < 4; ++q) {
            int f  = q * 256 + tid;        // 0..1023
            int r  = f >> 3;
            int c4 = (f & 7) * 4;
            cp16(xdst + (uint32_t)(r * XS_ST + c4) * 4, xsrc + (size_t)r * D_DIM + c4);
            cp16(edst + (uint32_t)(r * XS_ST + c4) * 4, esrc + (size_t)r * D_DIM + c4);
        }
        asm volatile("cp.async.commit_group;" ::: "memory");
    };

    issue(0, 0);

#pragma unroll 1
    for (int ks = 0; ks < N_STAGES; ++ks) {
        if (ks + 1 < N_STAGES) {
            issue(ks + 1, (ks + 1) & 1);
            asm volatile("cp.async.wait_group 1;" ::: "memory");
        } else {
            asm volatile("cp.async.wait_group 0;" ::: "memory");
        }
        __syncthreads();

        const float* xs = smem + (ks & 1) * BUF_FLOATS;
        const float* es = xs + TILE_FLOATS;

#pragma unroll
        for (int kk = 0; kk < KS / 8; ++kk) {
            const int k0 = kk * 8 + qt;
            // B fragments (4 n-tiles): hi/lo
            uint32_t bh[8], bl[8];
#pragma unroll
            for (int nt = 0; nt < 4; ++nt) {
                int n0 = warpCol * 32 + nt * 8 + quad;
                tf32_split(es[n0 * XS_ST + k0],     bh[nt * 2],     bl[nt * 2]);
                tf32_split(es[n0 * XS_ST + k0 + 4], bh[nt * 2 + 1], bl[nt * 2 + 1]);
            }
#pragma unroll
            for (int mt = 0; mt < 4; ++mt) {
                int r0 = warpRow * 64 + mt * 16 + quad;
                uint32_t ah[4], al[4];
                tf32_split(xs[r0 * XS_ST + k0],           ah[0], al[0]);
                tf32_split(xs[(r0 + 8) * XS_ST + k0],     ah[1], al[1]);
                tf32_split(xs[r0 * XS_ST + k0 + 4],       ah[2], al[2]);
                tf32_split(xs[(r0 + 8) * XS_ST + k0 + 4], ah[3], al[3]);
#pragma unroll
                for (int nt = 0; nt < 4; ++nt) {
                    mma_tf32(d[mt][nt], ah[0], ah[1], ah[2], ah[3], bh[nt*2], bh[nt*2+1]);
                    mma_tf32(d[mt][nt], ah[0], ah[1], ah[2], ah[3], bl[nt*2], bl[nt*2+1]);
                    mma_tf32(d[mt][nt], al[0], al[1], al[2], al[3], bh[nt*2], bh[nt*2+1]);
                }
            }
        }
        __syncthreads();   // done reading this buffer before it is refilled
    }

    // ---- epilogue: score = esq - 2*dot, per-row argmin ----
    float* sMin = smem;                 // 128*4 floats
    int*   sIdx = (int*)(smem + 512);   // 128*4 ints

#pragma unroll
    for (int mt = 0; mt < 4; ++mt) {
#pragma unroll
        for (int h = 0; h < 2; ++h) {
            float bmin = 3.4e38f;
            int   bidx = 0;
#pragma unroll
            for (int nt = 0; nt < 4; ++nt) {
                int col = codeBase + warpCol * 32 + nt * 8 + 2 * qt;
                float2 eq = *(const float2*)(g_esq + col);
                float s0 = fmaf(-2.f, d[mt][nt][2 * h],     eq.x);
                float s1 = fmaf(-2.f, d[mt][nt][2 * h + 1], eq.y);
                if (s0 < bmin) { bmin = s0; bidx = col; }
                if (s1 < bmin) { bmin = s1; bidx = col + 1; }
            }
            // reduce across the quad (qt bits), keep lowest index on ties
#pragma unroll
            for (int o = 1; o <= 2; o <<= 1) {
                float vo = __shfl_xor_sync(0xffffffffu, bmin, o);
                int   io = __shfl_xor_sync(0xffffffffu, bidx, o);
                if (vo < bmin || (vo == bmin && io < bidx)) { bmin = vo; bidx = io; }
            }
            if (qt == 0) {
                int rowLocal = warpRow * 64 + mt * 16 + h * 8 + quad;
                sMin[rowLocal * 4 + warpCol] = bmin;
                sIdx[rowLocal * 4 + warpCol] = bidx;
            }
        }
    }
    __syncthreads();
    if (tid < BM) {
        float bm = sMin[tid * 4];
        int   bi = sIdx[tid * 4];
#pragma unroll
        for (int c = 1; c < 4; ++c) {
            float v  = sMin[tid * 4 + c];
            int   ix = sIdx[tid * 4 + c];
            if (v < bm || (v == bm && ix < bi)) { bm = v; bi = ix; }
        }
        size_t o = (size_t)(rowBase + tid) * N_CT + blockIdx.x;
        g_pmin[o] = bm;
        g_pidx[o] = bi;
    }
}

// ============================ merge partial argmins ============================
__global__ void vq_merge_kernel() {
    int row = blockIdx.x * blockDim.x + threadIdx.x;
    if (row >= N_TOK) return;
    const float* pm = g_pmin + (size_t)row * N_CT;
    const int*   pi = g_pidx + (size_t)row * N_CT;
    float bm = pm[0];
    int   bi = pi[0];
#pragma unroll 8
    for (int c = 1; c < N_CT; ++c) {
        float v  = pm[c];
        int   ix = pi[c];
        if (v < bm || (v == bm && ix < bi)) { bm = v; bi = ix; }
    }
    g_idx[row] = bi;
}

// ============================ gather + loss partials + counts ============================
__global__ void vq_gather_kernel(const float* __restrict__ X, const float* __restrict__ E,
                                 float* __restrict__ outQ, float* __restrict__ outIdx,
                                 int writeExtras) {
    __shared__ float warpSums[8];
    int lwarp = threadIdx.x >> 5;
    int lane  = threadIdx.x & 31;
    int row   = blockIdx.x * 8 + lwarp;

    int idx = g_idx[row];
    const float4* e4 = (const float4*)(E + (size_t)idx * D_DIM);
    const float4* x4 = (const float4*)(X + (size_t)row * D_DIM);
    float4*       o4 = (float4*)(outQ + (size_t)row * D_DIM);

    float s = 0.f;
#pragma unroll
    for (int q = 0; q < 2; ++q) {
        float4 e = e4[lane + 32 * q];
        float4 x = x4[lane + 32 * q];
        float dx = e.x - x.x, dy = e.y - x.y, dz = e.z - x.z, dw = e.w - x.w;
        float4 o;
        o.x = x.x + dx; o.y = x.y + dy; o.z = x.z + dz; o.w = x.w + dw;
        o4[lane + 32 * q] = o;
        s += dx * dx + dy * dy + dz * dz + dw * dw;
    }
#pragma unroll
    for (int o = 16; o; o >>= 1) s += __shfl_xor_sync(0xffffffffu, s, o);
    if (lane == 0) {
        warpSums[lwarp] = s;
        atomicAdd(&g_counts[idx], 1);
        if (writeExtras) outIdx[row] = (float)idx;
    }
    __syncthreads();
    if (threadIdx.x == 0) {
        float bs = 0.f;
#pragma unroll
        for (int w = 0; w < 8; ++w) bs += warpSums[w];
        g_blocksum[blockIdx.x] = bs;
    }
}

// ============================ finalize: loss + perplexity ============================
__global__ void vq_finalize_kernel(float* __restrict__ outLoss, float* __restrict__ outPerp) {
    __shared__ float sh[256];
    int tid = threadIdx.x;

    float ss = 0.f;
    for (int b = tid; b < GATHER_BLOCKS; b += 256) ss += g_blocksum[b];
    sh[tid] = ss;
    __syncthreads();
    for (int o = 128; o; o >>= 1) {
        if (tid < o) sh[tid] += sh[tid + o];
        __syncthreads();
    }
    float sumsq = sh[0];
    __syncthreads();

    const float invN = 1.f / (float)N_TOK;
    float ent = 0.f;
    for (int k = tid; k < K_CODE; k += 256) {
        int c = g_counts[k];
        if (c > 0) {
            float p = (float)c * invN;
            ent += p * logf(p + 1e-10f);
        }
    }
    sh[tid] = ent;
    __syncthreads();
    for (int o = 128; o; o >>= 1) {
        if (tid < o) sh[tid] += sh[tid + o];
        __syncthreads();
    }
    if (tid == 0) {
        outLoss[0] = 0.25f * sumsq / (float)(N_TOK * D_DIM);
        outPerp[0] = expf(-sh[0]);
    }
}

// ============================ launcher ============================
extern "C" void kernel_launch(void* const* d_in, const int* in_sizes, int n_in,
                              void* d_out, int out_size) {
    const float* X = (const float*)d_in[0];
    const float* E = (const float*)d_in[1];
    float* out = (float*)d_out;

    float* outQ    = out;
    float* outIdx  = out + (size_t)N_TOK * D_DIM;
    float* outLoss = outIdx + N_TOK;
    float* outPerp = outLoss + 1;
    int writeExtras = (out_size >= N_TOK * D_DIM + N_TOK + 2) ? 1 : 0;

    cudaFuncSetAttribute(vq_mma_kernel,
                         cudaFuncAttributeMaxDynamicSharedMemorySize, SMEM_BYTES);

    vq_zero_kernel<<<(K_CODE + 255) / 256, 256>>>();
    vq_esq_kernel<<<K_CODE / 8, 256>>>(E);
    dim3 grid(N_CT, N_TOK / BM);   // 64 x 128
    vq_mma_kernel<<<grid, 256, SMEM_BYTES>>>(X, E);
    vq_merge_kernel<<<(N_TOK + 255) / 256, 256>>>();
    vq_gather_kernel<<<GATHER_BLOCKS, 256>>>(X, E, outQ, outIdx, writeExtras);
    if (writeExtras) vq_finalize_kernel<<<1, 256>>>(outLoss, outPerp);
}

// round 5
// speedup vs baseline: 6.4087x; 1.4692x over previous
#include <cuda_runtime.h>
#include <cuda_fp16.h>
#include <cstdint>

// VectorQuantizer on GB300 (sm_103a) — Round 5: 2xFP16-split mma.sync m16n8k16 distance GEMM
// inputs  : d_in[0] = X [16,1024,256] f32  (N=16384, D=256)
//           d_in[1] = E [8192,256]    f32  (K=8192)
// output  : d_out f32 = [ quantized_sg (N*D) | indices (N) | loss (1) | perplexity (1) ]

#define N_TOK  16384
#define D_DIM  256
#define K_CODE 8192

#define BM 128
#define BN 128
#define KS 32
#define N_STAGES (D_DIM / KS)      // 8
#define HS 36                      // h-tile row stride in halfs (conflict-free frags)

// smem layout (bytes)
#define RAW_BUF  32768             // X(16384) + E(16384) raw fp32 per buffer
#define HT_SIZE  (128 * HS * 2)    // 9216 per half-tile
#define OFF_RAW  0                 // 2 buffers: 65536
#define OFF_XH0  65536
#define OFF_XH1  (OFF_XH0 + HT_SIZE)
#define OFF_EH0  (OFF_XH1 + HT_SIZE)
#define OFF_EH1  (OFF_EH0 + HT_SIZE)
#define SMEM_BYTES (OFF_EH1 + HT_SIZE)   // 102400

#define N_CT (K_CODE / BN)         // 64
#define GATHER_BLOCKS (N_TOK / 8)  // 2048

__device__ float g_esq[K_CODE];
__device__ float g_pmin[N_TOK * N_CT];
__device__ int   g_pidx[N_TOK * N_CT];
__device__ int   g_counts[K_CODE];
__device__ float g_blocksum[GATHER_BLOCKS];

// ============================ helpers ============================
__device__ __forceinline__ uint32_t smem_u32(const void* p) {
    uint32_t a;
    asm("{ .reg .u64 t; cvta.to.shared.u64 t, %1; cvt.u32.u64 %0, t; }" : "=r"(a) : "l"(p));
    return a;
}
__device__ __forceinline__ void cp16(uint32_t dst, const void* src) {
    asm volatile("cp.async.ca.shared.global [%0], [%1], 16;" :: "r"(dst), "l"(src));
}
__device__ __forceinline__ void mma_f16(float* d, uint32_t a0, uint32_t a1, uint32_t a2,
                                        uint32_t a3, uint32_t b0, uint32_t b1) {
    asm volatile(
        "mma.sync.aligned.m16n8k16.row.col.f32.f16.f16.f32 "
        "{%0,%1,%2,%3}, {%4,%5,%6,%7}, {%8,%9}, {%0,%1,%2,%3};"
        : "+f"(d[0]), "+f"(d[1]), "+f"(d[2]), "+f"(d[3])
        : "r"(a0), "r"(a1), "r"(a2), "r"(a3), "r"(b0), "r"(b1));
}
__device__ __forceinline__ void h_split(float v, __half& h0, __half& h1) {
    h0 = __float2half_rn(v);
    h1 = __float2half_rn(v - __half2float(h0));
}

// ============================ esq (+zero counts) ============================
__global__ void vq_esq_kernel(const float* __restrict__ E) {
    int gwarp = (blockIdx.x * blockDim.x + threadIdx.x) >> 5;
    int lane  = threadIdx.x & 31;
    if (gwarp >= K_CODE) return;
    const float* row = E + (size_t)gwarp * D_DIM;
    float s = 0.f;
#pragma unroll
    for (int q = 0; q < D_DIM / 32; ++q) {
        float v = row[lane + 32 * q];
        s = fmaf(v, v, s);
    }
#pragma unroll
    for (int o = 16; o; o >>= 1) s += __shfl_xor_sync(0xffffffffu, s, o);
    if (lane == 0) { g_esq[gwarp] = s; g_counts[gwarp] = 0; }
}

// ============================ distance GEMM + partial argmin ============================
__global__ void __launch_bounds__(256, 2)
vq_mma_kernel(const float* __restrict__ X, const float* __restrict__ E) {
    extern __shared__ char smem[];
    float*  rawf = (float*)smem;
    __half* xh0  = (__half*)(smem + OFF_XH0);
    __half* xh1  = (__half*)(smem + OFF_XH1);
    __half* eh0  = (__half*)(smem + OFF_EH0);
    __half* eh1  = (__half*)(smem + OFF_EH1);

    const int tid  = threadIdx.x;
    const int wid  = tid >> 5;
    const int lane = tid & 31;
    const int quad = lane >> 2;     // 0..7
    const int qt   = lane & 3;      // 0..3
    const int warpRow = wid >> 2;   // 0..1 (64 rows each)
    const int warpCol = wid & 3;    // 0..3 (32 cols each)
    const int rowBase  = blockIdx.y * BM;
    const int codeBase = blockIdx.x * BN;
    const uint32_t sb = smem_u32(smem);

    float d[4][4][4];
#pragma unroll
    for (int mt = 0; mt < 4; ++mt)
#pragma unroll
        for (int nt = 0; nt < 4; ++nt)
#pragma unroll
            for (int r = 0; r < 4; ++r) d[mt][nt][r] = 0.f;

    // raw fill: X tile [128][32] + E tile [128][32] fp32, linear (no pad)
    auto issue = [&](int ks, int buf) {
        const float* xsrc = X + (size_t)rowBase * D_DIM + ks * KS;
        const float* esrc = E + (size_t)codeBase * D_DIM + ks * KS;
        uint32_t base = sb + (uint32_t)buf * RAW_BUF;
#pragma unroll
        for (int q = 0; q < 4; ++q) {
            int f  = q * 256 + tid;       // 0..1023 float4 slots
            int r  = f >> 3;
            int c4 = (f & 7) * 4;
            cp16(base + (uint32_t)(r * KS + c4) * 4, xsrc + (size_t)r * D_DIM + c4);
            cp16(base + 16384u + (uint32_t)(r * KS + c4) * 4, esrc + (size_t)r * D_DIM + c4);
        }
        asm volatile("cp.async.commit_group;" ::: "memory");
    };

    issue(0, 0);

#pragma unroll 1
    for (int ks = 0; ks < N_STAGES; ++ks) {
        if (ks + 1 < N_STAGES) {
            issue(ks + 1, (ks + 1) & 1);
            asm volatile("cp.async.wait_group 1;" ::: "memory");
        } else {
            asm volatile("cp.async.wait_group 0;" ::: "memory");
        }
        __syncthreads();   // raw[ks&1] ready; previous MMA done reading h-tiles

        // ---- split pass: raw fp32 -> fp16 h0/h1 tiles ----
        {
            const float* rb = rawf + (ks & 1) * (RAW_BUF / 4);
#pragma unroll
            for (int q = 0; q < 8; ++q) {
                int f  = (q & 3) * 256 + tid;
                int r  = f >> 3;
                int c4 = (f & 7) * 4;
                const float* src = rb + (q < 4 ? 0 : 4096) + r * KS + c4;
                __half* d0 = (q < 4 ? xh0 : eh0) + r * HS + c4;
                __half* d1 = (q < 4 ? xh1 : eh1) + r * HS + c4;
                float4 v = *(const float4*)src;
                __half a0, a1, b0, b1, c0, c1, e0, e1;
                h_split(v.x, a0, a1); h_split(v.y, b0, b1);
                h_split(v.z, c0, c1); h_split(v.w, e0, e1);
                *(half2*)(d0)     = __halves2half2(a0, b0);
                *(half2*)(d0 + 2) = __halves2half2(c0, e0);
                *(half2*)(d1)     = __halves2half2(a1, b1);
                *(half2*)(d1 + 2) = __halves2half2(c1, e1);
            }
        }
        __syncthreads();   // h-tiles ready for all warps

        // ---- MMA: 2 k16 steps ----
#pragma unroll
        for (int kk = 0; kk < KS / 16; ++kk) {
            const int k0 = kk * 16 + 2 * qt;
            // B fragments: 4 n-tiles, h0/h1
            uint32_t bh0[8], bh1[8];
#pragma unroll
            for (int nt = 0; nt < 4; ++nt) {
                int n0 = warpCol * 32 + nt * 8 + quad;
                bh0[nt * 2]     = *(const uint32_t*)(eh0 + n0 * HS + k0);
                bh0[nt * 2 + 1] = *(const uint32_t*)(eh0 + n0 * HS + k0 + 8);
                bh1[nt * 2]     = *(const uint32_t*)(eh1 + n0 * HS + k0);
                bh1[nt * 2 + 1] = *(const uint32_t*)(eh1 + n0 * HS + k0 + 8);
            }
#pragma unroll
            for (int mt = 0; mt < 4; ++mt) {
                int r0 = warpRow * 64 + mt * 16 + quad;
                uint32_t ah0[4], ah1[4];
                ah0[0] = *(const uint32_t*)(xh0 + r0 * HS + k0);
                ah0[1] = *(const uint32_t*)(xh0 + (r0 + 8) * HS + k0);
                ah0[2] = *(const uint32_t*)(xh0 + r0 * HS + k0 + 8);
                ah0[3] = *(const uint32_t*)(xh0 + (r0 + 8) * HS + k0 + 8);
                ah1[0] = *(const uint32_t*)(xh1 + r0 * HS + k0);
                ah1[1] = *(const uint32_t*)(xh1 + (r0 + 8) * HS + k0);
                ah1[2] = *(const uint32_t*)(xh1 + r0 * HS + k0 + 8);
                ah1[3] = *(const uint32_t*)(xh1 + (r0 + 8) * HS + k0 + 8);
#pragma unroll
                for (int nt = 0; nt < 4; ++nt) {
                    mma_f16(d[mt][nt], ah0[0], ah0[1], ah0[2], ah0[3], bh0[nt*2], bh0[nt*2+1]);
                    mma_f16(d[mt][nt], ah0[0], ah0[1], ah0[2], ah0[3], bh1[nt*2], bh1[nt*2+1]);
                    mma_f16(d[mt][nt], ah1[0], ah1[1], ah1[2], ah1[3], bh0[nt*2], bh0[nt*2+1]);
                }
            }
        }
    }

    // ---- epilogue: score = esq - 2*dot, per-row argmin over this code tile ----
    float* sMin = (float*)smem;
    int*   sIdx = (int*)(smem + 2048);

#pragma unroll
    for (int mt = 0; mt < 4; ++mt) {
#pragma unroll
        for (int h = 0; h < 2; ++h) {
            float bmin = 3.4e38f;
            int   bidx = 0;
#pragma unroll
            for (int nt = 0; nt < 4; ++nt) {
                int col = codeBase + warpCol * 32 + nt * 8 + 2 * qt;
                float2 eq = *(const float2*)(g_esq + col);
                float s0 = fmaf(-2.f, d[mt][nt][2 * h],     eq.x);
                float s1 = fmaf(-2.f, d[mt][nt][2 * h + 1], eq.y);
                if (s0 < bmin) { bmin = s0; bidx = col; }
                if (s1 < bmin) { bmin = s1; bidx = col + 1; }
            }
#pragma unroll
            for (int o = 1; o <= 2; o <<= 1) {
                float vo = __shfl_xor_sync(0xffffffffu, bmin, o);
                int   io = __shfl_xor_sync(0xffffffffu, bidx, o);
                if (vo < bmin || (vo == bmin && io < bidx)) { bmin = vo; bidx = io; }
            }
            if (qt == 0) {
                int rowLocal = warpRow * 64 + mt * 16 + h * 8 + quad;
                sMin[rowLocal * 4 + warpCol] = bmin;
                sIdx[rowLocal * 4 + warpCol] = bidx;
            }
        }
    }
    __syncthreads();
    if (tid < BM) {
        float bm = sMin[tid * 4];
        int   bi = sIdx[tid * 4];
#pragma unroll
        for (int c = 1; c < 4; ++c) {
            float v  = sMin[tid * 4 + c];
            int   ix = sIdx[tid * 4 + c];
            if (v < bm || (v == bm && ix < bi)) { bm = v; bi = ix; }
        }
        size_t o = (size_t)(rowBase + tid) * N_CT + blockIdx.x;
        g_pmin[o] = bm;
        g_pidx[o] = bi;
    }
}

// ============================ gather (+fused argmin merge) ============================
__global__ void vq_gather_kernel(const float* __restrict__ X, const float* __restrict__ E,
                                 float* __restrict__ outQ, float* __restrict__ outIdx,
                                 int writeExtras) {
    __shared__ float warpSums[8];
    int lwarp = threadIdx.x >> 5;
    int lane  = threadIdx.x & 31;
    int row   = blockIdx.x * 8 + lwarp;

    // merge 64 per-tile partials with a warp shfl reduction (ties -> lower index)
    const float* pm = g_pmin + (size_t)row * N_CT;
    const int*   pi = g_pidx + (size_t)row * N_CT;
    float bm = pm[lane];
    int   bi = pi[lane];
    {
        float m2 = pm[lane + 32];
        int   i2 = pi[lane + 32];
        if (m2 < bm || (m2 == bm && i2 < bi)) { bm = m2; bi = i2; }
    }
#pragma unroll
    for (int o = 16; o; o >>= 1) {
        float vo = __shfl_xor_sync(0xffffffffu, bm, o);
        int   io = __shfl_xor_sync(0xffffffffu, bi, o);
        if (vo < bm || (vo == bm && io < bi)) { bm = vo; bi = io; }
    }
    int idx = bi;   // identical in all lanes

    const float4* e4 = (const float4*)(E + (size_t)idx * D_DIM);
    const float4* x4 = (const float4*)(X + (size_t)row * D_DIM);
    float4*       o4 = (float4*)(outQ + (size_t)row * D_DIM);

    float s = 0.f;
#pragma unroll
    for (int q = 0; q < 2; ++q) {
        float4 e = e4[lane + 32 * q];
        float4 x = x4[lane + 32 * q];
        float dx = e.x - x.x, dy = e.y - x.y, dz = e.z - x.z, dw = e.w - x.w;
        float4 o;
        o.x = x.x + dx; o.y = x.y + dy; o.z = x.z + dz; o.w = x.w + dw;
        o4[lane + 32 * q] = o;
        s += dx * dx + dy * dy + dz * dz + dw * dw;
    }
#pragma unroll
    for (int o = 16; o; o >>= 1) s += __shfl_xor_sync(0xffffffffu, s, o);
    if (lane == 0) {
        warpSums[lwarp] = s;
        atomicAdd(&g_counts[idx], 1);
        if (writeExtras) outIdx[row] = (float)idx;
    }
    __syncthreads();
    if (threadIdx.x == 0) {
        float bs = 0.f;
#pragma unroll
        for (int w = 0; w < 8; ++w) bs += warpSums[w];
        g_blocksum[blockIdx.x] = bs;
    }
}

// ============================ finalize: loss + perplexity ============================
__global__ void vq_finalize_kernel(float* __restrict__ outLoss, float* __restrict__ outPerp) {
    __shared__ float sh[256];
    int tid = threadIdx.x;

    float ss = 0.f;
    for (int b = tid; b < GATHER_BLOCKS; b += 256) ss += g_blocksum[b];
    sh[tid] = ss;
    __syncthreads();
    for (int o = 128; o; o >>= 1) {
        if (tid < o) sh[tid] += sh[tid + o];
        __syncthreads();
    }
    float sumsq = sh[0];
    __syncthreads();

    const float invN = 1.f / (float)N_TOK;
    float ent = 0.f;
    for (int k = tid; k < K_CODE; k += 256) {
        int c = g_counts[k];
        if (c > 0) {
            float p = (float)c * invN;
            ent += p * logf(p + 1e-10f);
        }
    }
    sh[tid] = ent;
    __syncthreads();
    for (int o = 128; o; o >>= 1) {
        if (tid < o) sh[tid] += sh[tid + o];
        __syncthreads();
    }
    if (tid == 0) {
        outLoss[0] = 0.25f * sumsq / (float)(N_TOK * D_DIM);
        outPerp[0] = expf(-sh[0]);
    }
}

// ============================ launcher ============================
extern "C" void kernel_launch(void* const* d_in, const int* in_sizes, int n_in,
                              void* d_out, int out_size) {
    const float* X = (const float*)d_in[0];
    const float* E = (const float*)d_in[1];
    float* out = (float*)d_out;

    float* outQ    = out;
    float* outIdx  = out + (size_t)N_TOK * D_DIM;
    float* outLoss = outIdx + N_TOK;
    float* outPerp = outLoss + 1;
    int writeExtras = (out_size >= N_TOK * D_DIM + N_TOK + 2) ? 1 : 0;

    cudaFuncSetAttribute(vq_mma_kernel,
                         cudaFuncAttributeMaxDynamicSharedMemorySize, SMEM_BYTES);

    vq_esq_kernel<<<K_CODE / 8, 256>>>(E);
    dim3 grid(N_CT, N_TOK / BM);   // 64 x 128
    vq_mma_kernel<<<grid, 256, SMEM_BYTES>>>(X, E);
    vq_gather_kernel<<<GATHER_BLOCKS, 256>>>(X, E, outQ, outIdx, writeExtras);
    if (writeExtras) vq_finalize_kernel<<<1, 256>>>(outLoss, outPerp);
}

// round 6
// speedup vs baseline: 7.6501x; 1.1937x over previous
#include <cuda_runtime.h>
#include <cuda_fp16.h>
#include <cstdint>

// VectorQuantizer on GB300 (sm_103a) — Round 6: precomputed fp16-split + pure-MMA hot loop
// inputs  : d_in[0] = X [16,1024,256] f32  (N=16384, D=256)
//           d_in[1] = E [8192,256]    f32  (K=8192)
// output  : d_out f32 = [ quantized_sg (N*D) | indices (N) | loss (1) | perplexity (1) ]

#define N_TOK  16384
#define D_DIM  256
#define K_CODE 8192

#define BM 128
#define BN 128
#define KS 32
#define N_STAGES (D_DIM / KS)      // 8
#define HS 40                      // tile row stride in halfs (80B: 16B-aligned, conflict-free frags)

#define TILE_B  (128 * HS * 2)     // 10240 bytes per tile
#define BUF_B   (4 * TILE_B)       // xh0,xh1,eh0,eh1 per buffer = 40960
#define SMEM_BYTES (2 * BUF_B)     // 81920

#define N_CT (K_CODE / BN)         // 64
#define GATHER_BLOCKS (N_TOK / 8)  // 2048

__device__ __half g_Xh0[N_TOK * D_DIM];
__device__ __half g_Xh1[N_TOK * D_DIM];
__device__ __half g_Eh0[K_CODE * D_DIM];
__device__ __half g_Eh1[K_CODE * D_DIM];
__device__ float g_esq[K_CODE];
__device__ float g_pmin[N_TOK * N_CT];
__device__ int   g_pidx[N_TOK * N_CT];
__device__ int   g_counts[K_CODE];
__device__ float g_blocksum[GATHER_BLOCKS];
__device__ int   g_done;

// ============================ helpers ============================
__device__ __forceinline__ uint32_t smem_u32(const void* p) {
    uint32_t a;
    asm("{ .reg .u64 t; cvta.to.shared.u64 t, %1; cvt.u32.u64 %0, t; }" : "=r"(a) : "l"(p));
    return a;
}
__device__ __forceinline__ void cp16(uint32_t dst, const void* src) {
    asm volatile("cp.async.ca.shared.global [%0], [%1], 16;" :: "r"(dst), "l"(src));
}
__device__ __forceinline__ void mma_f16(float* d, uint32_t a0, uint32_t a1, uint32_t a2,
                                        uint32_t a3, uint32_t b0, uint32_t b1) {
    asm volatile(
        "mma.sync.aligned.m16n8k16.row.col.f32.f16.f16.f32 "
        "{%0,%1,%2,%3}, {%4,%5,%6,%7}, {%8,%9}, {%0,%1,%2,%3};"
        : "+f"(d[0]), "+f"(d[1]), "+f"(d[2]), "+f"(d[3])
        : "r"(a0), "r"(a1), "r"(a2), "r"(a3), "r"(b0), "r"(b1));
}

// ============================ prep: fp32 -> fp16 hi/lo pairs ============================
__global__ void vq_prep_kernel(const float* __restrict__ X, const float* __restrict__ E) {
    const int NX4 = N_TOK * D_DIM / 4;
    const int NT4 = NX4 + K_CODE * D_DIM / 4;
    for (int t = blockIdx.x * blockDim.x + threadIdx.x; t < NT4; t += gridDim.x * blockDim.x) {
        bool isX = t < NX4;
        int  e4  = isX ? t : t - NX4;
        float4 v = isX ? ((const float4*)X)[e4] : ((const float4*)E)[e4];
        __half h0x = __float2half_rn(v.x), h0y = __float2half_rn(v.y);
        __half h0z = __float2half_rn(v.z), h0w = __float2half_rn(v.w);
        __half h1x = __float2half_rn(v.x - __half2float(h0x));
        __half h1y = __float2half_rn(v.y - __half2float(h0y));
        __half h1z = __float2half_rn(v.z - __half2float(h0z));
        __half h1w = __float2half_rn(v.w - __half2float(h0w));
        half2 p0 = __halves2half2(h0x, h0y), p1 = __halves2half2(h0z, h0w);
        half2 q0 = __halves2half2(h1x, h1y), q1 = __halves2half2(h1z, h1w);
        __half* d0 = (isX ? g_Xh0 : g_Eh0) + e4 * 4;
        __half* d1 = (isX ? g_Xh1 : g_Eh1) + e4 * 4;
        *(half2*)(d0) = p0; *(half2*)(d0 + 2) = p1;
        *(half2*)(d1) = q0; *(half2*)(d1 + 2) = q1;
    }
}

// ============================ esq (+zero counts, done flag) ============================
__global__ void vq_esq_kernel(const float* __restrict__ E) {
    int gwarp = (blockIdx.x * blockDim.x + threadIdx.x) >> 5;
    int lane  = threadIdx.x & 31;
    if (blockIdx.x == 0 && threadIdx.x == 0) g_done = 0;
    if (gwarp >= K_CODE) return;
    const float* row = E + (size_t)gwarp * D_DIM;
    float s = 0.f;
#pragma unroll
    for (int q = 0; q < D_DIM / 32; ++q) {
        float v = row[lane + 32 * q];
        s = fmaf(v, v, s);
    }
#pragma unroll
    for (int o = 16; o; o >>= 1) s += __shfl_xor_sync(0xffffffffu, s, o);
    if (lane == 0) { g_esq[gwarp] = s; g_counts[gwarp] = 0; }
}

// ============================ distance GEMM + partial argmin ============================
__global__ void __launch_bounds__(256, 2)
vq_mma_kernel() {
    extern __shared__ char smem[];

    const int tid  = threadIdx.x;
    const int wid  = tid >> 5;
    const int lane = tid & 31;
    const int quad = lane >> 2;
    const int qt   = lane & 3;
    const int warpRow = wid >> 2;   // 0..1 (64 rows each)
    const int warpCol = wid & 3;    // 0..3 (32 cols each)
    const int rowBase  = blockIdx.y * BM;
    const int codeBase = blockIdx.x * BN;
    const uint32_t sb = smem_u32(smem);

    float d[4][4][4];
#pragma unroll
    for (int mt = 0; mt < 4; ++mt)
#pragma unroll
        for (int nt = 0; nt < 4; ++nt)
#pragma unroll
            for (int r = 0; r < 4; ++r) d[mt][nt][r] = 0.f;

    // stage loader: 4 fp16 tiles [128][KS], dest rows stride HS
    auto issue = [&](int ks, int buf) {
        const char* s0 = (const char*)(g_Xh0 + (size_t)rowBase * D_DIM + ks * KS);
        const char* s1 = (const char*)(g_Xh1 + (size_t)rowBase * D_DIM + ks * KS);
        const char* s2 = (const char*)(g_Eh0 + (size_t)codeBase * D_DIM + ks * KS);
        const char* s3 = (const char*)(g_Eh1 + (size_t)codeBase * D_DIM + ks * KS);
        uint32_t base = sb + (uint32_t)buf * BUF_B;
#pragma unroll
        for (int q = 0; q < 2; ++q) {
            int f = q * 256 + tid;      // 0..511 chunks per tile
            int r = f >> 2;
            int c = f & 3;
            uint32_t off = (uint32_t)r * (HS * 2) + (uint32_t)c * 16;
            size_t   gof = (size_t)r * (D_DIM * 2) + (size_t)c * 16;
            cp16(base + 0 * TILE_B + off, s0 + gof);
            cp16(base + 1 * TILE_B + off, s1 + gof);
            cp16(base + 2 * TILE_B + off, s2 + gof);
            cp16(base + 3 * TILE_B + off, s3 + gof);
        }
        asm volatile("cp.async.commit_group;" ::: "memory");
    };

    issue(0, 0);

#pragma unroll 1
    for (int ks = 0; ks < N_STAGES; ++ks) {
        if (ks + 1 < N_STAGES) {
            issue(ks + 1, (ks + 1) & 1);
            asm volatile("cp.async.wait_group 1;" ::: "memory");
        } else {
            asm volatile("cp.async.wait_group 0;" ::: "memory");
        }
        __syncthreads();   // buf[ks&1] data ready for all warps

        const __half* xh0 = (const __half*)(smem + (ks & 1) * BUF_B);
        const __half* xh1 = (const __half*)(smem + (ks & 1) * BUF_B + TILE_B);
        const __half* eh0 = (const __half*)(smem + (ks & 1) * BUF_B + 2 * TILE_B);
        const __half* eh1 = (const __half*)(smem + (ks & 1) * BUF_B + 3 * TILE_B);

#pragma unroll
        for (int kk = 0; kk < KS / 16; ++kk) {
            const int k0 = kk * 16 + 2 * qt;
            uint32_t bh0[8], bh1[8];
#pragma unroll
            for (int nt = 0; nt < 4; ++nt) {
                int n0 = warpCol * 32 + nt * 8 + quad;
                bh0[nt * 2]     = *(const uint32_t*)(eh0 + n0 * HS + k0);
                bh0[nt * 2 + 1] = *(const uint32_t*)(eh0 + n0 * HS + k0 + 8);
                bh1[nt * 2]     = *(const uint32_t*)(eh1 + n0 * HS + k0);
                bh1[nt * 2 + 1] = *(const uint32_t*)(eh1 + n0 * HS + k0 + 8);
            }
#pragma unroll
            for (int mt = 0; mt < 4; ++mt) {
                int r0 = warpRow * 64 + mt * 16 + quad;
                uint32_t ah0[4], ah1[4];
                ah0[0] = *(const uint32_t*)(xh0 + r0 * HS + k0);
                ah0[1] = *(const uint32_t*)(xh0 + (r0 + 8) * HS + k0);
                ah0[2] = *(const uint32_t*)(xh0 + r0 * HS + k0 + 8);
                ah0[3] = *(const uint32_t*)(xh0 + (r0 + 8) * HS + k0 + 8);
                ah1[0] = *(const uint32_t*)(xh1 + r0 * HS + k0);
                ah1[1] = *(const uint32_t*)(xh1 + (r0 + 8) * HS + k0);
                ah1[2] = *(const uint32_t*)(xh1 + r0 * HS + k0 + 8);
                ah1[3] = *(const uint32_t*)(xh1 + (r0 + 8) * HS + k0 + 8);
#pragma unroll
                for (int nt = 0; nt < 4; ++nt) {
                    mma_f16(d[mt][nt], ah0[0], ah0[1], ah0[2], ah0[3], bh0[nt*2], bh0[nt*2+1]);
                    mma_f16(d[mt][nt], ah0[0], ah0[1], ah0[2], ah0[3], bh1[nt*2], bh1[nt*2+1]);
                    mma_f16(d[mt][nt], ah1[0], ah1[1], ah1[2], ah1[3], bh0[nt*2], bh0[nt*2+1]);
                }
            }
        }
        __syncthreads();   // all warps done reading buf[ks&1] before it is re-filled
    }

    // ---- epilogue: score = esq - 2*dot, per-row argmin over this code tile ----
    float* sMin = (float*)smem;
    int*   sIdx = (int*)(smem + 2048);

#pragma unroll
    for (int mt = 0; mt < 4; ++mt) {
#pragma unroll
        for (int h = 0; h < 2; ++h) {
            float bmin = 3.4e38f;
            int   bidx = 0;
#pragma unroll
            for (int nt = 0; nt < 4; ++nt) {
                int col = codeBase + warpCol * 32 + nt * 8 + 2 * qt;
                float2 eq = *(const float2*)(g_esq + col);
                float s0 = fmaf(-2.f, d[mt][nt][2 * h],     eq.x);
                float s1 = fmaf(-2.f, d[mt][nt][2 * h + 1], eq.y);
                if (s0 < bmin) { bmin = s0; bidx = col; }
                if (s1 < bmin) { bmin = s1; bidx = col + 1; }
            }
#pragma unroll
            for (int o = 1; o <= 2; o <<= 1) {
                float vo = __shfl_xor_sync(0xffffffffu, bmin, o);
                int   io = __shfl_xor_sync(0xffffffffu, bidx, o);
                if (vo < bmin || (vo == bmin && io < bidx)) { bmin = vo; bidx = io; }
            }
            if (qt == 0) {
                int rowLocal = warpRow * 64 + mt * 16 + h * 8 + quad;
                sMin[rowLocal * 4 + warpCol] = bmin;
                sIdx[rowLocal * 4 + warpCol] = bidx;
            }
        }
    }
    __syncthreads();
    if (tid < BM) {
        float bm = sMin[tid * 4];
        int   bi = sIdx[tid * 4];
#pragma unroll
        for (int c = 1; c < 4; ++c) {
            float v  = sMin[tid * 4 + c];
            int   ix = sIdx[tid * 4 + c];
            if (v < bm || (v == bm && ix < bi)) { bm = v; bi = ix; }
        }
        size_t o = (size_t)(rowBase + tid) * N_CT + blockIdx.x;
        g_pmin[o] = bm;
        g_pidx[o] = bi;
    }
}

// ============================ gather + merge + (last block) finalize ============================
__global__ void vq_gather_kernel(const float* __restrict__ X, const float* __restrict__ E,
                                 float* __restrict__ outQ, float* __restrict__ outIdx,
                                 float* __restrict__ outLoss, float* __restrict__ outPerp,
                                 int writeExtras) {
    __shared__ float warpSums[8];
    __shared__ int   isLast;
    int lwarp = threadIdx.x >> 5;
    int lane  = threadIdx.x & 31;
    int row   = blockIdx.x * 8 + lwarp;

    // merge 64 per-tile partials (warp shfl reduction, ties -> lower index)
    const float* pm = g_pmin + (size_t)row * N_CT;
    const int*   pi = g_pidx + (size_t)row * N_CT;
    float bm = pm[lane];
    int   bi = pi[lane];
    {
        float m2 = pm[lane + 32];
        int   i2 = pi[lane + 32];
        if (m2 < bm || (m2 == bm && i2 < bi)) { bm = m2; bi = i2; }
    }
#pragma unroll
    for (int o = 16; o; o >>= 1) {
        float vo = __shfl_xor_sync(0xffffffffu, bm, o);
        int   io = __shfl_xor_sync(0xffffffffu, bi, o);
        if (vo < bm || (vo == bm && io < bi)) { bm = vo; bi = io; }
    }
    int idx = bi;

    const float4* e4 = (const float4*)(E + (size_t)idx * D_DIM);
    const float4* x4 = (const float4*)(X + (size_t)row * D_DIM);
    float4*       o4 = (float4*)(outQ + (size_t)row * D_DIM);

    float s = 0.f;
#pragma unroll
    for (int q = 0; q < 2; ++q) {
        float4 e = e4[lane + 32 * q];
        float4 x = x4[lane + 32 * q];
        float dx = e.x - x.x, dy = e.y - x.y, dz = e.z - x.z, dw = e.w - x.w;
        float4 o;
        o.x = x.x + dx; o.y = x.y + dy; o.z = x.z + dz; o.w = x.w + dw;
        o4[lane + 32 * q] = o;
        s += dx * dx + dy * dy + dz * dz + dw * dw;
    }
#pragma unroll
    for (int o = 16; o; o >>= 1) s += __shfl_xor_sync(0xffffffffu, s, o);
    if (lane == 0) {
        warpSums[lwarp] = s;
        atomicAdd(&g_counts[idx], 1);
        if (writeExtras) outIdx[row] = (float)idx;
    }
    __syncthreads();
    if (threadIdx.x == 0) {
        float bs = 0.f;
#pragma unroll
        for (int w = 0; w < 8; ++w) bs += warpSums[w];
        g_blocksum[blockIdx.x] = bs;
        __threadfence();
        int t = atomicAdd(&g_done, 1);
        isLast = (t == GATHER_BLOCKS - 1) ? 1 : 0;
    }
    __syncthreads();

    if (isLast) {
        // ---- finalize: loss + perplexity (deterministic fixed-order partials) ----
        __shared__ float sh[256];
        int tid = threadIdx.x;
        float ss = 0.f;
        for (int b = tid; b < GATHER_BLOCKS; b += 256) ss += g_blocksum[b];
        sh[tid] = ss;
        __syncthreads();
        for (int o = 128; o; o >>= 1) {
            if (tid < o) sh[tid] += sh[tid + o];
            __syncthreads();
        }
        float sumsq = sh[0];
        __syncthreads();

        const float invN = 1.f / (float)N_TOK;
        float ent = 0.f;
        for (int k = tid; k < K_CODE; k += 256) {
            int c = g_counts[k];
            if (c > 0) {
                float p = (float)c * invN;
                ent += p * logf(p + 1e-10f);
            }
        }
        sh[tid] = ent;
        __syncthreads();
        for (int o = 128; o; o >>= 1) {
            if (tid < o) sh[tid] += sh[tid + o];
            __syncthreads();
        }
        if (tid == 0 && writeExtras) {
            outLoss[0] = 0.25f * sumsq / (float)(N_TOK * D_DIM);
            outPerp[0] = expf(-sh[0]);
        }
    }
}

// ============================ launcher ============================
extern "C" void kernel_launch(void* const* d_in, const int* in_sizes, int n_in,
                              void* d_out, int out_size) {
    const float* X = (const float*)d_in[0];
    const float* E = (const float*)d_in[1];
    float* out = (float*)d_out;

    float* outQ    = out;
    float* outIdx  = out + (size_t)N_TOK * D_DIM;
    float* outLoss = outIdx + N_TOK;
    float* outPerp = outLoss + 1;
    int writeExtras = (out_size >= N_TOK * D_DIM + N_TOK + 2) ? 1 : 0;

    cudaFuncSetAttribute(vq_mma_kernel,
                         cudaFuncAttributeMaxDynamicSharedMemorySize, SMEM_BYTES);

    vq_prep_kernel<<<1024, 256>>>(X, E);
    vq_esq_kernel<<<K_CODE / 8, 256>>>(E);
    dim3 grid(N_CT, N_TOK / BM);   // 64 x 128
    vq_mma_kernel<<<grid, 256, SMEM_BYTES>>>();
    vq_gather_kernel<<<GATHER_BLOCKS, 256>>>(X, E, outQ, outIdx, outLoss, outPerp, writeExtras);
}

// round 7
// speedup vs baseline: 8.6343x; 1.1286x over previous
#include <cuda_runtime.h>
#include <cuda_fp16.h>
#include <cstdint>

// VectorQuantizer on GB300 (sm_103a) — Round 7: ldmatrix fragment loads
// inputs  : d_in[0] = X [16,1024,256] f32  (N=16384, D=256)
//           d_in[1] = E [8192,256]    f32  (K=8192)
// output  : d_out f32 = [ quantized_sg (N*D) | indices (N) | loss (1) | perplexity (1) ]

#define N_TOK  16384
#define D_DIM  256
#define K_CODE 8192

#define BM 128
#define BN 128
#define KS 32
#define N_STAGES (D_DIM / KS)      // 8
#define HS 40                      // tile row stride in halfs (80B rows: LDSM conflict-free)

#define TILE_B  (128 * HS * 2)     // 10240 bytes per tile
#define BUF_B   (4 * TILE_B)       // xh0,xh1,eh0,eh1 = 40960
#define SMEM_BYTES (2 * BUF_B)     // 81920
#define MT_STRIDE (16 * HS * 2)    // 1280 bytes per 16 rows

#define N_CT (K_CODE / BN)         // 64
#define GATHER_BLOCKS (N_TOK / 8)  // 2048

__device__ __half g_Xh0[N_TOK * D_DIM];
__device__ __half g_Xh1[N_TOK * D_DIM];
__device__ __half g_Eh0[K_CODE * D_DIM];
__device__ __half g_Eh1[K_CODE * D_DIM];
__device__ float g_esq[K_CODE];
__device__ float g_pmin[N_TOK * N_CT];
__device__ int   g_pidx[N_TOK * N_CT];
__device__ int   g_counts[K_CODE];
__device__ float g_blocksum[GATHER_BLOCKS];
__device__ int   g_done;

// ============================ helpers ============================
__device__ __forceinline__ uint32_t smem_u32(const void* p) {
    uint32_t a;
    asm("{ .reg .u64 t; cvta.to.shared.u64 t, %1; cvt.u32.u64 %0, t; }" : "=r"(a) : "l"(p));
    return a;
}
__device__ __forceinline__ void cp16(uint32_t dst, const void* src) {
    asm volatile("cp.async.ca.shared.global [%0], [%1], 16;" :: "r"(dst), "l"(src));
}
__device__ __forceinline__ void mma_f16(float* d, uint32_t a0, uint32_t a1, uint32_t a2,
                                        uint32_t a3, uint32_t b0, uint32_t b1) {
    asm volatile(
        "mma.sync.aligned.m16n8k16.row.col.f32.f16.f16.f32 "
        "{%0,%1,%2,%3}, {%4,%5,%6,%7}, {%8,%9}, {%0,%1,%2,%3};"
        : "+f"(d[0]), "+f"(d[1]), "+f"(d[2]), "+f"(d[3])
        : "r"(a0), "r"(a1), "r"(a2), "r"(a3), "r"(b0), "r"(b1));
}
#define LDSM4(r0, r1, r2, r3, addr) \
    asm volatile("ldmatrix.sync.aligned.m8n8.x4.shared.b16 {%0,%1,%2,%3}, [%4];" \
                 : "=r"(r0), "=r"(r1), "=r"(r2), "=r"(r3) : "r"(addr))

// ============================ prep: fp32 -> fp16 hi/lo pairs ============================
__global__ void vq_prep_kernel(const float* __restrict__ X, const float* __restrict__ E) {
    const int NX4 = N_TOK * D_DIM / 4;
    const int NT4 = NX4 + K_CODE * D_DIM / 4;
    for (int t = blockIdx.x * blockDim.x + threadIdx.x; t < NT4; t += gridDim.x * blockDim.x) {
        bool isX = t < NX4;
        int  e4  = isX ? t : t - NX4;
        float4 v = isX ? ((const float4*)X)[e4] : ((const float4*)E)[e4];
        __half h0x = __float2half_rn(v.x), h0y = __float2half_rn(v.y);
        __half h0z = __float2half_rn(v.z), h0w = __float2half_rn(v.w);
        __half h1x = __float2half_rn(v.x - __half2float(h0x));
        __half h1y = __float2half_rn(v.y - __half2float(h0y));
        __half h1z = __float2half_rn(v.z - __half2float(h0z));
        __half h1w = __float2half_rn(v.w - __half2float(h0w));
        half2 p0 = __halves2half2(h0x, h0y), p1 = __halves2half2(h0z, h0w);
        half2 q0 = __halves2half2(h1x, h1y), q1 = __halves2half2(h1z, h1w);
        __half* d0 = (isX ? g_Xh0 : g_Eh0) + e4 * 4;
        __half* d1 = (isX ? g_Xh1 : g_Eh1) + e4 * 4;
        *(half2*)(d0) = p0; *(half2*)(d0 + 2) = p1;
        *(half2*)(d1) = q0; *(half2*)(d1 + 2) = q1;
    }
}

// ============================ esq (+zero counts, done flag) ============================
__global__ void vq_esq_kernel(const float* __restrict__ E) {
    int gwarp = (blockIdx.x * blockDim.x + threadIdx.x) >> 5;
    int lane  = threadIdx.x & 31;
    if (blockIdx.x == 0 && threadIdx.x == 0) g_done = 0;
    if (gwarp >= K_CODE) return;
    const float* row = E + (size_t)gwarp * D_DIM;
    float s = 0.f;
#pragma unroll
    for (int q = 0; q < D_DIM / 32; ++q) {
        float v = row[lane + 32 * q];
        s = fmaf(v, v, s);
    }
#pragma unroll
    for (int o = 16; o; o >>= 1) s += __shfl_xor_sync(0xffffffffu, s, o);
    if (lane == 0) { g_esq[gwarp] = s; g_counts[gwarp] = 0; }
}

// ============================ distance GEMM + partial argmin ============================
__global__ void __launch_bounds__(256, 2)
vq_mma_kernel() {
    extern __shared__ char smem[];

    const int tid  = threadIdx.x;
    const int wid  = tid >> 5;
    const int lane = tid & 31;
    const int quad = lane >> 2;
    const int qt   = lane & 3;
    const int warpRow = wid >> 2;   // 0..1 (64 rows each)
    const int warpCol = wid & 3;    // 0..3 (32 cols each)
    const int rowBase  = blockIdx.y * BM;
    const int codeBase = blockIdx.x * BN;
    const uint32_t sb = smem_u32(smem);

    // LDSM per-lane base offsets (bytes)
    const int lr = lane & 7;
    const int lb = (lane >> 3) & 1;
    const int lc = lane >> 4;
    const uint32_t aOff = ((uint32_t)(warpRow * 64 + lb * 8 + lr) * HS + (uint32_t)lc * 8) * 2;
    const uint32_t bOff = ((uint32_t)(warpCol * 32 + lc * 8 + lr) * HS + (uint32_t)lb * 8) * 2;

    float d[4][4][4];
#pragma unroll
    for (int mt = 0; mt < 4; ++mt)
#pragma unroll
        for (int nt = 0; nt < 4; ++nt)
#pragma unroll
            for (int r = 0; r < 4; ++r) d[mt][nt][r] = 0.f;

    // stage loader: 4 fp16 tiles [128][KS], dest rows stride HS
    auto issue = [&](int ks, int buf) {
        const char* s0 = (const char*)(g_Xh0 + (size_t)rowBase * D_DIM + ks * KS);
        const char* s1 = (const char*)(g_Xh1 + (size_t)rowBase * D_DIM + ks * KS);
        const char* s2 = (const char*)(g_Eh0 + (size_t)codeBase * D_DIM + ks * KS);
        const char* s3 = (const char*)(g_Eh1 + (size_t)codeBase * D_DIM + ks * KS);
        uint32_t base = sb + (uint32_t)buf * BUF_B;
#pragma unroll
        for (int q = 0; q < 2; ++q) {
            int f = q * 256 + tid;      // 0..511 16B chunks per tile
            int r = f >> 2;
            int c = f & 3;
            uint32_t off = (uint32_t)r * (HS * 2) + (uint32_t)c * 16;
            size_t   gof = (size_t)r * (D_DIM * 2) + (size_t)c * 16;
            cp16(base + 0 * TILE_B + off, s0 + gof);
            cp16(base + 1 * TILE_B + off, s1 + gof);
            cp16(base + 2 * TILE_B + off, s2 + gof);
            cp16(base + 3 * TILE_B + off, s3 + gof);
        }
        asm volatile("cp.async.commit_group;" ::: "memory");
    };

    issue(0, 0);

#pragma unroll 1
    for (int ks = 0; ks < N_STAGES; ++ks) {
        if (ks + 1 < N_STAGES) {
            issue(ks + 1, (ks + 1) & 1);
            asm volatile("cp.async.wait_group 1;" ::: "memory");
        } else {
            asm volatile("cp.async.wait_group 0;" ::: "memory");
        }
        __syncthreads();   // buf[ks&1] data ready

        const uint32_t bufB = sb + (uint32_t)(ks & 1) * BUF_B;

#pragma unroll
        for (int kk = 0; kk < KS / 16; ++kk) {
            const uint32_t kByte = (uint32_t)kk * 32;
            // B fragments: x4 covers two n-tiles each
            uint32_t bh0[8], bh1[8];
            LDSM4(bh0[0], bh0[1], bh0[2], bh0[3], bufB + 2 * TILE_B + bOff + kByte);
            LDSM4(bh0[4], bh0[5], bh0[6], bh0[7], bufB + 2 * TILE_B + bOff + MT_STRIDE + kByte);
            LDSM4(bh1[0], bh1[1], bh1[2], bh1[3], bufB + 3 * TILE_B + bOff + kByte);
            LDSM4(bh1[4], bh1[5], bh1[6], bh1[7], bufB + 3 * TILE_B + bOff + MT_STRIDE + kByte);
#pragma unroll
            for (int mt = 0; mt < 4; ++mt) {
                uint32_t ah0[4], ah1[4];
                LDSM4(ah0[0], ah0[1], ah0[2], ah0[3],
                      bufB + 0 * TILE_B + aOff + (uint32_t)mt * MT_STRIDE + kByte);
                LDSM4(ah1[0], ah1[1], ah1[2], ah1[3],
                      bufB + 1 * TILE_B + aOff + (uint32_t)mt * MT_STRIDE + kByte);
#pragma unroll
                for (int nt = 0; nt < 4; ++nt) {
                    mma_f16(d[mt][nt], ah0[0], ah0[1], ah0[2], ah0[3], bh0[nt*2], bh0[nt*2+1]);
                    mma_f16(d[mt][nt], ah0[0], ah0[1], ah0[2], ah0[3], bh1[nt*2], bh1[nt*2+1]);
                    mma_f16(d[mt][nt], ah1[0], ah1[1], ah1[2], ah1[3], bh0[nt*2], bh0[nt*2+1]);
                }
            }
        }
        __syncthreads();   // all warps done reading buf[ks&1] before refill
    }

    // ---- epilogue: score = esq - 2*dot, per-row argmin over this code tile ----
    float* sMin = (float*)smem;
    int*   sIdx = (int*)(smem + 2048);

#pragma unroll
    for (int mt = 0; mt < 4; ++mt) {
#pragma unroll
        for (int h = 0; h < 2; ++h) {
            float bmin = 3.4e38f;
            int   bidx = 0;
#pragma unroll
            for (int nt = 0; nt < 4; ++nt) {
                int col = codeBase + warpCol * 32 + nt * 8 + 2 * qt;
                float2 eq = *(const float2*)(g_esq + col);
                float s0 = fmaf(-2.f, d[mt][nt][2 * h],     eq.x);
                float s1 = fmaf(-2.f, d[mt][nt][2 * h + 1], eq.y);
                if (s0 < bmin) { bmin = s0; bidx = col; }
                if (s1 < bmin) { bmin = s1; bidx = col + 1; }
            }
#pragma unroll
            for (int o = 1; o <= 2; o <<= 1) {
                float vo = __shfl_xor_sync(0xffffffffu, bmin, o);
                int   io = __shfl_xor_sync(0xffffffffu, bidx, o);
                if (vo < bmin || (vo == bmin && io < bidx)) { bmin = vo; bidx = io; }
            }
            if (qt == 0) {
                int rowLocal = warpRow * 64 + mt * 16 + h * 8 + quad;
                sMin[rowLocal * 4 + warpCol] = bmin;
                sIdx[rowLocal * 4 + warpCol] = bidx;
            }
        }
    }
    __syncthreads();
    if (tid < BM) {
        float bm = sMin[tid * 4];
        int   bi = sIdx[tid * 4];
#pragma unroll
        for (int c = 1; c < 4; ++c) {
            float v  = sMin[tid * 4 + c];
            int   ix = sIdx[tid * 4 + c];
            if (v < bm || (v == bm && ix < bi)) { bm = v; bi = ix; }
        }
        size_t o = (size_t)(rowBase + tid) * N_CT + blockIdx.x;
        g_pmin[o] = bm;
        g_pidx[o] = bi;
    }
}

// ============================ gather + merge + (last block) finalize ============================
__global__ void vq_gather_kernel(const float* __restrict__ X, const float* __restrict__ E,
                                 float* __restrict__ outQ, float* __restrict__ outIdx,
                                 float* __restrict__ outLoss, float* __restrict__ outPerp,
                                 int writeExtras) {
    __shared__ float warpSums[8];
    __shared__ int   isLast;
    int lwarp = threadIdx.x >> 5;
    int lane  = threadIdx.x & 31;
    int row   = blockIdx.x * 8 + lwarp;

    const float* pm = g_pmin + (size_t)row * N_CT;
    const int*   pi = g_pidx + (size_t)row * N_CT;
    float bm = pm[lane];
    int   bi = pi[lane];
    {
        float m2 = pm[lane + 32];
        int   i2 = pi[lane + 32];
        if (m2 < bm || (m2 == bm && i2 < bi)) { bm = m2; bi = i2; }
    }
#pragma unroll
    for (int o = 16; o; o >>= 1) {
        float vo = __shfl_xor_sync(0xffffffffu, bm, o);
        int   io = __shfl_xor_sync(0xffffffffu, bi, o);
        if (vo < bm || (vo == bm && io < bi)) { bm = vo; bi = io; }
    }
    int idx = bi;

    const float4* e4 = (const float4*)(E + (size_t)idx * D_DIM);
    const float4* x4 = (const float4*)(X + (size_t)row * D_DIM);
    float4*       o4 = (float4*)(outQ + (size_t)row * D_DIM);

    float s = 0.f;
#pragma unroll
    for (int q = 0; q < 2; ++q) {
        float4 e = e4[lane + 32 * q];
        float4 x = x4[lane + 32 * q];
        float dx = e.x - x.x, dy = e.y - x.y, dz = e.z - x.z, dw = e.w - x.w;
        float4 o;
        o.x = x.x + dx; o.y = x.y + dy; o.z = x.z + dz; o.w = x.w + dw;
        o4[lane + 32 * q] = o;
        s += dx * dx + dy * dy + dz * dz + dw * dw;
    }
#pragma unroll
    for (int o = 16; o; o >>= 1) s += __shfl_xor_sync(0xffffffffu, s, o);
    if (lane == 0) {
        warpSums[lwarp] = s;
        atomicAdd(&g_counts[idx], 1);
        if (writeExtras) outIdx[row] = (float)idx;
    }
    __syncthreads();
    if (threadIdx.x == 0) {
        float bs = 0.f;
#pragma unroll
        for (int w = 0; w < 8; ++w) bs += warpSums[w];
        g_blocksum[blockIdx.x] = bs;
        __threadfence();
        int t = atomicAdd(&g_done, 1);
        isLast = (t == GATHER_BLOCKS - 1) ? 1 : 0;
    }
    __syncthreads();

    if (isLast) {
        __shared__ float sh[256];
        int tid = threadIdx.x;
        float ss = 0.f;
        for (int b = tid; b < GATHER_BLOCKS; b += 256) ss += g_blocksum[b];
        sh[tid] = ss;
        __syncthreads();
        for (int o = 128; o; o >>= 1) {
            if (tid < o) sh[tid] += sh[tid + o];
            __syncthreads();
        }
        float sumsq = sh[0];
        __syncthreads();

        const float invN = 1.f / (float)N_TOK;
        float ent = 0.f;
        for (int k = tid; k < K_CODE; k += 256) {
            int c = g_counts[k];
            if (c > 0) {
                float p = (float)c * invN;
                ent += p * logf(p + 1e-10f);
            }
        }
        sh[tid] = ent;
        __syncthreads();
        for (int o = 128; o; o >>= 1) {
            if (tid < o) sh[tid] += sh[tid + o];
            __syncthreads();
        }
        if (tid == 0 && writeExtras) {
            outLoss[0] = 0.25f * sumsq / (float)(N_TOK * D_DIM);
            outPerp[0] = expf(-sh[0]);
        }
    }
}

// ============================ launcher ============================
extern "C" void kernel_launch(void* const* d_in, const int* in_sizes, int n_in,
                              void* d_out, int out_size) {
    const float* X = (const float*)d_in[0];
    const float* E = (const float*)d_in[1];
    float* out = (float*)d_out;

    float* outQ    = out;
    float* outIdx  = out + (size_t)N_TOK * D_DIM;
    float* outLoss = outIdx + N_TOK;
    float* outPerp = outLoss + 1;
    int writeExtras = (out_size >= N_TOK * D_DIM + N_TOK + 2) ? 1 : 0;

    cudaFuncSetAttribute(vq_mma_kernel,
                         cudaFuncAttributeMaxDynamicSharedMemorySize, SMEM_BYTES);

    vq_prep_kernel<<<1024, 256>>>(X, E);
    vq_esq_kernel<<<K_CODE / 8, 256>>>(E);
    dim3 grid(N_CT, N_TOK / BM);   // 64 x 128
    vq_mma_kernel<<<grid, 256, SMEM_BYTES>>>();
    vq_gather_kernel<<<GATHER_BLOCKS, 256>>>(X, E, outQ, outIdx, outLoss, outPerp, writeExtras);
}

// round 8
// speedup vs baseline: 9.1507x; 1.0598x over previous
#include <cuda_runtime.h>
#include <cuda_fp16.h>
#include <cstdint>

// VectorQuantizer on GB300 (sm_103a) — Round 8: 1-pass fp16 approx MMA + exact refine
// inputs  : d_in[0] = X [16,1024,256] f32  (N=16384, D=256)
//           d_in[1] = E [8192,256]    f32  (K=8192)
// output  : d_out f32 = [ quantized_sg (N*D) | indices (N) | loss (1) | perplexity (1) ]

#define N_TOK  16384
#define D_DIM  256
#define K_CODE 8192

#define BM 128
#define BN 128
#define KS 32
#define N_STAGES (D_DIM / KS)      // 8
#define HS 40                      // tile row stride in halfs (80B rows: LDSM conflict-free)

#define TILE_B  (128 * HS * 2)     // 10240 bytes per tile
#define BUF_B   (2 * TILE_B)       // xh, eh per buffer = 20480
#define SMEM_BYTES (4 * BUF_B)     // 4-stage pipeline = 81920
#define MT_STRIDE (16 * HS * 2)    // 1280 bytes per 16 rows

#define N_CT (K_CODE / BN)         // 64
#define GATHER_BLOCKS (N_TOK / 8)  // 2048
#define DELTA 0.02f                // refine window (>> max approx error ~8e-3)

__device__ __half g_Xh[N_TOK * D_DIM];
__device__ __half g_Eh[K_CODE * D_DIM];
__device__ float g_esq[K_CODE];
__device__ float g_p1min[N_TOK * N_CT];
__device__ int   g_p1idx[N_TOK * N_CT];
__device__ float g_p2min[N_TOK * N_CT];
__device__ int   g_p2idx[N_TOK * N_CT];
__device__ int   g_counts[K_CODE];
__device__ float g_blocksum[GATHER_BLOCKS];
__device__ int   g_done;

// ============================ helpers ============================
__device__ __forceinline__ uint32_t smem_u32(const void* p) {
    uint32_t a;
    asm("{ .reg .u64 t; cvta.to.shared.u64 t, %1; cvt.u32.u64 %0, t; }" : "=r"(a) : "l"(p));
    return a;
}
__device__ __forceinline__ void cp16(uint32_t dst, const void* src) {
    asm volatile("cp.async.ca.shared.global [%0], [%1], 16;" :: "r"(dst), "l"(src));
}
__device__ __forceinline__ void mma_f16(float* d, uint32_t a0, uint32_t a1, uint32_t a2,
                                        uint32_t a3, uint32_t b0, uint32_t b1) {
    asm volatile(
        "mma.sync.aligned.m16n8k16.row.col.f32.f16.f16.f32 "
        "{%0,%1,%2,%3}, {%4,%5,%6,%7}, {%8,%9}, {%0,%1,%2,%3};"
        : "+f"(d[0]), "+f"(d[1]), "+f"(d[2]), "+f"(d[3])
        : "r"(a0), "r"(a1), "r"(a2), "r"(a3), "r"(b0), "r"(b1));
}
#define LDSM4(r0, r1, r2, r3, addr) \
    asm volatile("ldmatrix.sync.aligned.m8n8.x4.shared.b16 {%0,%1,%2,%3}, [%4];" \
                 : "=r"(r0), "=r"(r1), "=r"(r2), "=r"(r3) : "r"(addr))

// ordered best-2 update by (value, index)
__device__ __forceinline__ void upd2(float s, int c, float& m1, int& i1, float& m2, int& i2) {
    if (s < m1 || (s == m1 && c < i1)) { m2 = m1; i2 = i1; m1 = s; i1 = c; }
    else if (s < m2 || (s == m2 && c < i2)) { m2 = s; i2 = c; }
}

// ============================ prep: fp32 -> fp16 (hi only) ============================
__global__ void vq_prep_kernel(const float* __restrict__ X, const float* __restrict__ E) {
    const int NX4 = N_TOK * D_DIM / 4;
    const int NT4 = NX4 + K_CODE * D_DIM / 4;
    for (int t = blockIdx.x * blockDim.x + threadIdx.x; t < NT4; t += gridDim.x * blockDim.x) {
        bool isX = t < NX4;
        int  e4  = isX ? t : t - NX4;
        float4 v = isX ? ((const float4*)X)[e4] : ((const float4*)E)[e4];
        half2 p0 = __halves2half2(__float2half_rn(v.x), __float2half_rn(v.y));
        half2 p1 = __halves2half2(__float2half_rn(v.z), __float2half_rn(v.w));
        __half* d0 = (isX ? g_Xh : g_Eh) + e4 * 4;
        *(half2*)(d0) = p0; *(half2*)(d0 + 2) = p1;
    }
}

// ============================ esq (+zero counts, done flag) ============================
__global__ void vq_esq_kernel(const float* __restrict__ E) {
    int gwarp = (blockIdx.x * blockDim.x + threadIdx.x) >> 5;
    int lane  = threadIdx.x & 31;
    if (blockIdx.x == 0 && threadIdx.x == 0) g_done = 0;
    if (gwarp >= K_CODE) return;
    const float* row = E + (size_t)gwarp * D_DIM;
    float s = 0.f;
#pragma unroll
    for (int q = 0; q < D_DIM / 32; ++q) {
        float v = row[lane + 32 * q];
        s = fmaf(v, v, s);
    }
#pragma unroll
    for (int o = 16; o; o >>= 1) s += __shfl_xor_sync(0xffffffffu, s, o);
    if (lane == 0) { g_esq[gwarp] = s; g_counts[gwarp] = 0; }
}

// ============================ approx distance GEMM + best-2 per tile ============================
__global__ void __launch_bounds__(256, 2)
vq_mma_kernel() {
    extern __shared__ char smem[];

    const int tid  = threadIdx.x;
    const int wid  = tid >> 5;
    const int lane = tid & 31;
    const int quad = lane >> 2;
    const int qt   = lane & 3;
    const int warpRow = wid >> 2;   // 0..1 (64 rows each)
    const int warpCol = wid & 3;    // 0..3 (32 cols each)
    const int rowBase  = blockIdx.y * BM;
    const int codeBase = blockIdx.x * BN;
    const uint32_t sb = smem_u32(smem);

    // LDSM per-lane base offsets (bytes)
    const int lr = lane & 7;
    const int lb = (lane >> 3) & 1;
    const int lc = lane >> 4;
    const uint32_t aOff = ((uint32_t)(warpRow * 64 + lb * 8 + lr) * HS + (uint32_t)lc * 8) * 2;
    const uint32_t bOff = ((uint32_t)(warpCol * 32 + lc * 8 + lr) * HS + (uint32_t)lb * 8) * 2;

    float d[4][4][4];
#pragma unroll
    for (int mt = 0; mt < 4; ++mt)
#pragma unroll
        for (int nt = 0; nt < 4; ++nt)
#pragma unroll
            for (int r = 0; r < 4; ++r) d[mt][nt][r] = 0.f;

    // stage loader: X tile + E tile (fp16), dest rows stride HS
    auto issue = [&](int ks) {
        const char* s0 = (const char*)(g_Xh + (size_t)rowBase * D_DIM + ks * KS);
        const char* s1 = (const char*)(g_Eh + (size_t)codeBase * D_DIM + ks * KS);
        uint32_t base = sb + (uint32_t)(ks & 3) * BUF_B;
#pragma unroll
        for (int q = 0; q < 2; ++q) {
            int f = q * 256 + tid;      // 0..511 16B chunks per tile
            int r = f >> 2;
            int c = f & 3;
            uint32_t off = (uint32_t)r * (HS * 2) + (uint32_t)c * 16;
            size_t   gof = (size_t)r * (D_DIM * 2) + (size_t)c * 16;
            cp16(base + off, s0 + gof);
            cp16(base + TILE_B + off, s1 + gof);
        }
        asm volatile("cp.async.commit_group;" ::: "memory");
    };

    issue(0); issue(1); issue(2);

#pragma unroll 1
    for (int ks = 0; ks < N_STAGES; ++ks) {
        asm volatile("cp.async.wait_group 2;" ::: "memory");
        __syncthreads();   // stage ks data visible; all warps done with buf (ks-1)&3
        if (ks + 3 < N_STAGES) issue(ks + 3);
        else asm volatile("cp.async.commit_group;" ::: "memory");  // empty group keeps count uniform

        const uint32_t bufB = sb + (uint32_t)(ks & 3) * BUF_B;

#pragma unroll
        for (int kk = 0; kk < KS / 16; ++kk) {
            const uint32_t kByte = (uint32_t)kk * 32;
            uint32_t bh[8];
            LDSM4(bh[0], bh[1], bh[2], bh[3], bufB + TILE_B + bOff + kByte);
            LDSM4(bh[4], bh[5], bh[6], bh[7], bufB + TILE_B + bOff + MT_STRIDE + kByte);
#pragma unroll
            for (int mt = 0; mt < 4; ++mt) {
                uint32_t ah[4];
                LDSM4(ah[0], ah[1], ah[2], ah[3],
                      bufB + aOff + (uint32_t)mt * MT_STRIDE + kByte);
#pragma unroll
                for (int nt = 0; nt < 4; ++nt)
                    mma_f16(d[mt][nt], ah[0], ah[1], ah[2], ah[3], bh[nt*2], bh[nt*2+1]);
            }
        }
    }
    __syncthreads();   // compute done before smem reuse by epilogue

    // ---- epilogue: approx score = esq - 2*dot; best-2 per row over this tile ----
    float* sM1 = (float*)smem;                    // [128][4]
    int*   sI1 = (int*)(smem + 2048);
    float* sM2 = (float*)(smem + 4096);
    int*   sI2 = (int*)(smem + 6144);

#pragma unroll
    for (int mt = 0; mt < 4; ++mt) {
#pragma unroll
        for (int h = 0; h < 2; ++h) {
            float m1 = 3.4e38f, m2 = 3.4e38f;
            int   i1 = 0x7fffffff, i2 = 0x7fffffff;
#pragma unroll
            for (int nt = 0; nt < 4; ++nt) {
                int col = codeBase + warpCol * 32 + nt * 8 + 2 * qt;
                float2 eq = *(const float2*)(g_esq + col);
                upd2(fmaf(-2.f, d[mt][nt][2 * h],     eq.x), col,     m1, i1, m2, i2);
                upd2(fmaf(-2.f, d[mt][nt][2 * h + 1], eq.y), col + 1, m1, i1, m2, i2);
            }
#pragma unroll
            for (int o = 1; o <= 2; o <<= 1) {
                float om1 = __shfl_xor_sync(0xffffffffu, m1, o);
                int   oi1 = __shfl_xor_sync(0xffffffffu, i1, o);
                float om2 = __shfl_xor_sync(0xffffffffu, m2, o);
                int   oi2 = __shfl_xor_sync(0xffffffffu, i2, o);
                upd2(om1, oi1, m1, i1, m2, i2);
                upd2(om2, oi2, m1, i1, m2, i2);
            }
            if (qt == 0) {
                int rowLocal = warpRow * 64 + mt * 16 + h * 8 + quad;
                sM1[rowLocal * 4 + warpCol] = m1;
                sI1[rowLocal * 4 + warpCol] = i1;
                sM2[rowLocal * 4 + warpCol] = m2;
                sI2[rowLocal * 4 + warpCol] = i2;
            }
        }
    }
    __syncthreads();
    if (tid < BM) {
        float m1 = 3.4e38f, m2 = 3.4e38f;
        int   i1 = 0x7fffffff, i2 = 0x7fffffff;
#pragma unroll
        for (int c = 0; c < 4; ++c) {
            upd2(sM1[tid * 4 + c], sI1[tid * 4 + c], m1, i1, m2, i2);
            upd2(sM2[tid * 4 + c], sI2[tid * 4 + c], m1, i1, m2, i2);
        }
        size_t o = (size_t)(rowBase + tid) * N_CT + blockIdx.x;
        g_p1min[o] = m1; g_p1idx[o] = i1;
        g_p2min[o] = m2; g_p2idx[o] = i2;
    }
}

// ============================ gather + refine + (last block) finalize ============================
__global__ void vq_gather_kernel(const float* __restrict__ X, const float* __restrict__ E,
                                 float* __restrict__ outQ, float* __restrict__ outIdx,
                                 float* __restrict__ outLoss, float* __restrict__ outPerp,
                                 int writeExtras) {
    __shared__ float warpSums[8];
    __shared__ int   candList[8][16];
    __shared__ int   candCnt[8];
    __shared__ int   isLast;
    int lwarp = threadIdx.x >> 5;
    int lane  = threadIdx.x & 31;
    int row   = blockIdx.x * 8 + lwarp;

    if (lane == 0) candCnt[lwarp] = 0;
    __syncwarp();

    // gather candidates: best-2 per tile within DELTA of global approx min
    size_t pb = (size_t)row * N_CT;
    float v0 = g_p1min[pb + lane],      v1 = g_p1min[pb + lane + 32];
    int   x0 = g_p1idx[pb + lane],      x1 = g_p1idx[pb + lane + 32];
    float v2 = g_p2min[pb + lane],      v3 = g_p2min[pb + lane + 32];
    int   x2 = g_p2idx[pb + lane],      x3 = g_p2idx[pb + lane + 32];
    float mn = fminf(v0, v1);
#pragma unroll
    for (int o = 16; o; o >>= 1) mn = fminf(mn, __shfl_xor_sync(0xffffffffu, mn, o));
    float thr = mn + DELTA;
    if (v0 <= thr) { int p = atomicAdd(&candCnt[lwarp], 1); if (p < 16) candList[lwarp][p] = x0; }
    if (v1 <= thr) { int p = atomicAdd(&candCnt[lwarp], 1); if (p < 16) candList[lwarp][p] = x1; }
    if (v2 <= thr) { int p = atomicAdd(&candCnt[lwarp], 1); if (p < 16) candList[lwarp][p] = x2; }
    if (v3 <= thr) { int p = atomicAdd(&candCnt[lwarp], 1); if (p < 16) candList[lwarp][p] = x3; }
    __syncwarp();
    int cnt = candCnt[lwarp];
    if (cnt > 16) cnt = 16;

    // exact refine: fp32 score = esq - 2 * <x,e> for each candidate
    const float4* x4 = (const float4*)(X + (size_t)row * D_DIM);
    float4 xv0 = x4[lane], xv1 = x4[lane + 32];

    float bsc = 3.4e38f;
    int   bidx = 0x7fffffff;
    for (int j = 0; j < cnt; ++j) {
        int c = candList[lwarp][j];
        const float4* ec = (const float4*)(E + (size_t)c * D_DIM);
        float4 e0 = ec[lane], e1 = ec[lane + 32];
        float dt = xv0.x * e0.x;
        dt = fmaf(xv0.y, e0.y, dt);
        dt = fmaf(xv0.z, e0.z, dt);
        dt = fmaf(xv0.w, e0.w, dt);
        dt = fmaf(xv1.x, e1.x, dt);
        dt = fmaf(xv1.y, e1.y, dt);
        dt = fmaf(xv1.z, e1.z, dt);
        dt = fmaf(xv1.w, e1.w, dt);
#pragma unroll
        for (int o = 16; o; o >>= 1) dt += __shfl_xor_sync(0xffffffffu, dt, o);
        float sc = __ldg(&g_esq[c]) - 2.f * dt;
        if (sc < bsc || (sc == bsc && c < bidx)) { bsc = sc; bidx = c; }
    }
    int idx = bidx;   // identical in all lanes (dt fully reduced)

    const float4* e4 = (const float4*)(E + (size_t)idx * D_DIM);
    float4* o4 = (float4*)(outQ + (size_t)row * D_DIM);

    float s = 0.f;
    {
        float4 e = e4[lane];
        float dx = e.x - xv0.x, dy = e.y - xv0.y, dz = e.z - xv0.z, dw = e.w - xv0.w;
        float4 o; o.x = xv0.x + dx; o.y = xv0.y + dy; o.z = xv0.z + dz; o.w = xv0.w + dw;
        o4[lane] = o;
        s += dx * dx + dy * dy + dz * dz + dw * dw;
    }
    {
        float4 e = e4[lane + 32];
        float dx = e.x - xv1.x, dy = e.y - xv1.y, dz = e.z - xv1.z, dw = e.w - xv1.w;
        float4 o; o.x = xv1.x + dx; o.y = xv1.y + dy; o.z = xv1.z + dz; o.w = xv1.w + dw;
        o4[lane + 32] = o;
        s += dx * dx + dy * dy + dz * dz + dw * dw;
    }
#pragma unroll
    for (int o = 16; o; o >>= 1) s += __shfl_xor_sync(0xffffffffu, s, o);
    if (lane == 0) {
        warpSums[lwarp] = s;
        atomicAdd(&g_counts[idx], 1);
        if (writeExtras) outIdx[row] = (float)idx;
    }
    __syncthreads();
    if (threadIdx.x == 0) {
        float bs = 0.f;
#pragma unroll
        for (int w = 0; w < 8; ++w) bs += warpSums[w];
        g_blocksum[blockIdx.x] = bs;
        __threadfence();
        int t = atomicAdd(&g_done, 1);
        isLast = (t == GATHER_BLOCKS - 1) ? 1 : 0;
    }
    __syncthreads();

    if (isLast) {
        __shared__ float sh[256];
        int tid = threadIdx.x;
        float ss = 0.f;
        for (int b = tid; b < GATHER_BLOCKS; b += 256) ss += g_blocksum[b];
        sh[tid] = ss;
        __syncthreads();
        for (int o = 128; o; o >>= 1) {
            if (tid < o) sh[tid] += sh[tid + o];
            __syncthreads();
        }
        float sumsq = sh[0];
        __syncthreads();

        const float invN = 1.f / (float)N_TOK;
        float ent = 0.f;
        for (int k = tid; k < K_CODE; k += 256) {
            int c = g_counts[k];
            if (c > 0) {
                float p = (float)c * invN;
                ent += p * logf(p + 1e-10f);
            }
        }
        sh[tid] = ent;
        __syncthreads();
        for (int o = 128; o; o >>= 1) {
            if (tid < o) sh[tid] += sh[tid + o];
            __syncthreads();
        }
        if (tid == 0 && writeExtras) {
            outLoss[0] = 0.25f * sumsq / (float)(N_TOK * D_DIM);
            outPerp[0] = expf(-sh[0]);
        }
    }
}

// ============================ launcher ============================
extern "C" void kernel_launch(void* const* d_in, const int* in_sizes, int n_in,
                              void* d_out, int out_size) {
    const float* X = (const float*)d_in[0];
    const float* E = (const float*)d_in[1];
    float* out = (float*)d_out;

    float* outQ    = out;
    float* outIdx  = out + (size_t)N_TOK * D_DIM;
    float* outLoss = outIdx + N_TOK;
    float* outPerp = outLoss + 1;
    int writeExtras = (out_size >= N_TOK * D_DIM + N_TOK + 2) ? 1 : 0;

    cudaFuncSetAttribute(vq_mma_kernel,
                         cudaFuncAttributeMaxDynamicSharedMemorySize, SMEM_BYTES);

    vq_prep_kernel<<<1024, 256>>>(X, E);
    vq_esq_kernel<<<K_CODE / 8, 256>>>(E);
    dim3 grid(N_CT, N_TOK / BM);   // 64 x 128
    vq_mma_kernel<<<grid, 256, SMEM_BYTES>>>();
    vq_gather_kernel<<<GATHER_BLOCKS, 256>>>(X, E, outQ, outIdx, outLoss, outPerp, writeExtras);
}